// round 11
// baseline (speedup 1.0000x reference)
#include <cuda_runtime.h>

#define NB 16
#define NG 32
#define NLVL 5
#define A_TOTAL 65472
#define HI_T 0.5f
#define LO_T 0.4f

__constant__ int LVL_OFF[6] = {0, 49152, 61440, 64512, 65280, 65472};

// Phase-1 intermediates: per (b, level, g) best IoU + best anchor (local idx)
__device__ float d_gt_max[NB][NLVL][NG];
__device__ int   d_gt_arg[NB][NLVL][NG];

// Bit-exact IEEE f32 IoU matching the JAX reference evaluation order:
//   inter = max(x2-x1,0)*max(y2-y1,0)
//   denom = ((aa + ag) - inter) + 1e-9     (left-to-right)
//   iou   = inter / denom                   (round-to-nearest division)
// _rn intrinsics block FMA contraction and fast-math approximations.
__device__ __forceinline__ float iou_f(float4 a, float4 g) {
    float x1 = fmaxf(a.x, g.x);
    float y1 = fmaxf(a.y, g.y);
    float x2 = fminf(a.z, g.z);
    float y2 = fminf(a.w, g.w);
    float iw = fmaxf(__fsub_rn(x2, x1), 0.0f);
    float ih = fmaxf(__fsub_rn(y2, y1), 0.0f);
    float inter = __fmul_rn(iw, ih);
    float aa = __fmul_rn(__fsub_rn(a.z, a.x), __fsub_rn(a.w, a.y));
    float ag = __fmul_rn(__fsub_rn(g.z, g.x), __fsub_rn(g.w, g.y));
    float denom = __fadd_rn(__fsub_rn(__fadd_rn(aa, ag), inter), 1e-9f);
    return __fdiv_rn(inter, denom);
}

// combine keeping first-max (smaller index on tie)
__device__ __forceinline__ void combine(float& v, int& i, float v2, int i2) {
    if (v2 > v || (v2 == v && i2 < i)) { v = v2; i = i2; }
}

// ---------------------------------------------------------------------------
// Phase 1: one block (256 thr) per (b, g, li). Max + first-max argmax over
// the level's anchors. Tie-break: smaller anchor index wins (jnp.argmax).
// ---------------------------------------------------------------------------
__global__ void phase1_kernel(const float4* __restrict__ anchors,
                              const float4* __restrict__ bb) {
    int blk = blockIdx.x;
    int li = blk % NLVL;
    int g  = (blk / NLVL) % NG;
    int b  = blk / (NLVL * NG);

    float4 gt = bb[b * NG + g];
    int off = LVL_OFF[li];
    int n   = LVL_OFF[li + 1] - off;

    float best = -1.0f;
    int   bidx = 0x7fffffff;
    for (int i = threadIdx.x; i < n; i += blockDim.x) {
        float v = iou_f(__ldg(&anchors[off + i]), gt);
        if (v > best) { best = v; bidx = i; }   // indices ascend: '>' keeps first max
    }

    // warp butterfly reduction
    #pragma unroll
    for (int s = 16; s > 0; s >>= 1) {
        float v2 = __shfl_xor_sync(0xffffffffu, best, s);
        int   i2 = __shfl_xor_sync(0xffffffffu, bidx, s);
        combine(best, bidx, v2, i2);
    }

    __shared__ float sv[8];
    __shared__ int   si[8];
    int wid = threadIdx.x >> 5;
    if ((threadIdx.x & 31) == 0) { sv[wid] = best; si[wid] = bidx; }
    __syncthreads();

    if (threadIdx.x == 0) {
        #pragma unroll
        for (int w = 1; w < 8; w++) combine(best, bidx, sv[w], si[w]);
        d_gt_max[b][li][g] = best;
        d_gt_arg[b][li][g] = bidx;
    }
}

// ---------------------------------------------------------------------------
// Phase 2: one thread per (b, anchor).
// ---------------------------------------------------------------------------
__global__ void phase2_kernel(const float4* __restrict__ anchors,
                              const float4* __restrict__ bb,
                              const int* __restrict__ ids,
                              float* __restrict__ out) {
    int b = blockIdx.y;
    int a = blockIdx.x * 256 + threadIdx.x;

    __shared__ float4 sgt[NG];
    __shared__ int    sid[NG];
    __shared__ int    slvl[NG];   // gt_max_level per g
    __shared__ int    sarg[NG];   // gt_arg for THIS block's level

    // level of this block (uniform across block)
    int a0 = blockIdx.x * 256;
    int li = 0;
    while (a0 >= LVL_OFF[li + 1]) li++;

    if (threadIdx.x < NG) {
        int g = threadIdx.x;
        sgt[g] = bb[b * NG + g];
        sid[g] = ids[b * NG + g];
        float mv = d_gt_max[b][0][g];
        int   ml = 0;
        #pragma unroll
        for (int l = 1; l < NLVL; l++) {
            float v = d_gt_max[b][l][g];
            if (v > mv) { mv = v; ml = l; }   // first max over levels
        }
        slvl[g] = ml;
        sarg[g] = d_gt_arg[b][li][g];
    }
    __syncthreads();

    if (a >= A_TOTAL) return;

    float4 an = anchors[a];
    int a_loc = a - LVL_OFF[li];

    // argmax over g (first max)
    float maxov = -1.0f;
    int   arg = 0;
    #pragma unroll
    for (int g = 0; g < NG; g++) {
        float v = iou_f(an, sgt[g]);
        if (v > maxov) { maxov = v; arg = g; }
    }

    // forced assignment: last g with (gt_max_level==li && gt_arg==a_loc) wins
    int forced = -1;
    #pragma unroll
    for (int g = 0; g < NG; g++) {
        if (slvl[g] == li && sarg[g] == a_loc) forced = g;
    }

    bool pos;
    int aid;
    float4 gb;
    if (forced >= 0) {
        pos = true;
        aid = sid[forced];
        gb  = sgt[forced];
    } else {
        pos = (maxov >= HI_T);
        aid = sid[arg];
        gb  = sgt[arg];
    }

    int label = pos ? aid : ((maxov >= LO_T && maxov < HI_T) ? -1 : 0);

    float4 r = make_float4(0.f, 0.f, 0.f, 0.f);
    if (pos) {
        float aw = __fsub_rn(an.z, an.x);
        float ah = __fsub_rn(an.w, an.y);
        float ax = __fadd_rn(an.x, __fmul_rn(0.5f, aw));
        float ay = __fadd_rn(an.y, __fmul_rn(0.5f, ah));
        float gw = __fsub_rn(gb.z, gb.x);
        float gh = __fsub_rn(gb.w, gb.y);
        float gx = __fadd_rn(gb.x, __fmul_rn(0.5f, gw));
        float gy = __fadd_rn(gb.y, __fmul_rn(0.5f, gh));
        r = make_float4(__fdiv_rn(__fsub_rn(gx, ax), aw),
                        __fdiv_rn(__fsub_rn(gy, ay), ah),
                        logf(__fdiv_rn(gw, aw)),
                        logf(__fdiv_rn(gh, ah)));
    }

    // Output layout: labels (B*A) flattened first, then regs (B*A*4)
    out[(size_t)b * A_TOTAL + a] = (float)label;
    float4* rout = (float4*)(out + (size_t)NB * A_TOTAL);
    rout[(size_t)b * A_TOTAL + a] = r;
}

extern "C" void kernel_launch(void* const* d_in, const int* in_sizes, int n_in,
                              void* d_out, int out_size) {
    const float4* bb      = (const float4*)d_in[0];  // bb_coord (16,32,4) f32
    const int*    ids     = (const int*)d_in[1];     // bird_ids (16,32) i32
    const float4* anchors = (const float4*)d_in[2];  // anchors (65472,4) f32
    float* out = (float*)d_out;

    phase1_kernel<<<NB * NG * NLVL, 256>>>(anchors, bb);
    phase2_kernel<<<dim3((A_TOTAL + 255) / 256, NB), 256>>>(anchors, bb, ids, out);
}

// round 14
// speedup vs baseline: 5.1694x; 5.1694x over previous
#include <cuda_runtime.h>

#define NB 16
#define NG 32
#define NLVL 5
#define A_TOTAL 65472
#define ABLOCKS 256          // ceil(65472/256)
#define HI_T 0.5f
#define LO_T 0.4f

__constant__ int LVL_OFF[6] = {0, 49152, 61440, 64512, 65280, 65472};

// packed per-(b,level,g) first-max: (iou_bits << 32) | (0xFFFFFFFF - local_anchor_idx)
__device__ unsigned long long d_table[NB][NLVL][NG];
// per-(b,anchor) max IoU over g + first-max argmax
__device__ float d_pmax[NB][A_TOTAL];
__device__ int   d_parg[NB][A_TOTAL];

// ---------------------------------------------------------------------------
__global__ void init_table() {
    int i = blockIdx.x * blockDim.x + threadIdx.x;
    if (i < NB * NLVL * NG)
        ((unsigned long long*)d_table)[i] = 0ull;
}

// ---------------------------------------------------------------------------
// Fused pass: each thread = one (b, anchor). Computes all 32 IoUs ONCE
// (bit-exact _rn path; division skipped when inter==0 -> IoU exactly +0.0),
// keeps per-anchor max/argmax, and block-reduces per-g first-max into d_table
// in two 16-g rounds (32 KB static smem, no attribute needed).
// ---------------------------------------------------------------------------
__global__ void fused_kernel(const float4* __restrict__ anchors,
                             const float4* __restrict__ bb) {
    __shared__ unsigned long long s_pack[16][256];
    __shared__ float4 sgt[NG];
    __shared__ float  sag[NG];

    int b   = blockIdx.y;
    int tid = threadIdx.x;
    int a0  = blockIdx.x * 256;
    int a   = a0 + tid;

    int li = 0;
    while (a0 >= LVL_OFF[li + 1]) li++;

    if (tid < NG) {
        float4 g = bb[b * NG + tid];
        sgt[tid] = g;
        sag[tid] = __fmul_rn(__fsub_rn(g.z, g.x), __fsub_rn(g.w, g.y));
    }
    __syncthreads();

    bool valid = a < A_TOTAL;
    float4 an = anchors[valid ? a : 0];
    float aa = __fmul_rn(__fsub_rn(an.z, an.x), __fsub_rn(an.w, an.y));
    int a_loc = a - LVL_OFF[li];
    unsigned int inv = 0xFFFFFFFFu - (unsigned int)a_loc;
    int wid = tid >> 5, lane = tid & 31;

    float maxov = -1.0f;
    int   arg = 0;

    #pragma unroll
    for (int half = 0; half < 2; half++) {
        #pragma unroll
        for (int gg = 0; gg < 16; gg++) {
            int g = half * 16 + gg;
            float v = 0.0f;
            if (valid) {
                float4 gt = sgt[g];
                float x1 = fmaxf(an.x, gt.x);
                float y1 = fmaxf(an.y, gt.y);
                float x2 = fminf(an.z, gt.z);
                float y2 = fminf(an.w, gt.w);
                float iw = fmaxf(__fsub_rn(x2, x1), 0.0f);
                float ih = fmaxf(__fsub_rn(y2, y1), 0.0f);
                float inter = __fmul_rn(iw, ih);
                if (inter > 0.0f) {   // 0/denom == +0.0 exactly -> skip is bit-exact
                    float denom = __fadd_rn(__fsub_rn(__fadd_rn(aa, sag[g]), inter), 1e-9f);
                    v = __fdiv_rn(inter, denom);
                }
            }
            s_pack[gg][tid] = valid
                ? ((((unsigned long long)__float_as_uint(v)) << 32) | inv) : 0ull;
            if (v > maxov) { maxov = v; arg = g; }   // first-max over g
        }
        __syncthreads();

        // reduce this half's 16 g over the block: warp wid handles gg = wid*2, wid*2+1
        #pragma unroll
        for (int k = 0; k < 2; k++) {
            int gg = wid * 2 + k;
            unsigned long long m = s_pack[gg][lane];
            #pragma unroll
            for (int j = 1; j < 8; j++) {
                unsigned long long t = s_pack[gg][lane + 32 * j];
                if (t > m) m = t;
            }
            #pragma unroll
            for (int s = 16; s > 0; s >>= 1) {
                unsigned long long t = __shfl_xor_sync(0xffffffffu, m, s);
                if (t > m) m = t;
            }
            if (lane == 0) atomicMax(&d_table[b][li][half * 16 + gg], m);
        }
        __syncthreads();   // protect s_pack before next half overwrites
    }

    if (valid) { d_pmax[b][a] = maxov; d_parg[b][a] = arg; }
}

// ---------------------------------------------------------------------------
// Finalize: per (b, anchor) -> label + regression, using stored per-anchor
// max/argmax and the global per-(b,level,g) table. Forced assignment is a
// per-block smem scatter (last-g-wins, matching .at[].set()).
// ---------------------------------------------------------------------------
__global__ void finalize_kernel(const float4* __restrict__ anchors,
                                const float4* __restrict__ bb,
                                const int* __restrict__ ids,
                                float* __restrict__ out) {
    int b   = blockIdx.y;
    int tid = threadIdx.x;
    int a0  = blockIdx.x * 256;
    int a   = a0 + tid;

    __shared__ float4 sgt[NG];
    __shared__ int    sid[NG];
    __shared__ int    slvl[NG];
    __shared__ int    sarg[NG];
    __shared__ int    sforced[256];

    int li = 0;
    while (a0 >= LVL_OFF[li + 1]) li++;

    sforced[tid] = -1;
    if (tid < NG) {
        sgt[tid] = bb[b * NG + tid];
        sid[tid] = ids[b * NG + tid];
        unsigned long long p0 = d_table[b][0][tid];
        float mv = __uint_as_float((unsigned int)(p0 >> 32));
        int   ml = 0;
        #pragma unroll
        for (int l = 1; l < NLVL; l++) {
            unsigned long long p = d_table[b][l][tid];
            float v = __uint_as_float((unsigned int)(p >> 32));
            if (v > mv) { mv = v; ml = l; }   // first-max over levels
        }
        slvl[tid] = ml;
        unsigned long long pl = d_table[b][li][tid];
        sarg[tid] = (int)(0xFFFFFFFFu - (unsigned int)(pl & 0xFFFFFFFFu));
    }
    __syncthreads();

    if (tid == 0) {
        int base = a0 - LVL_OFF[li];   // block start as level-local index
        for (int g = 0; g < NG; g++) { // ascending g: last write wins
            if (slvl[g] == li) {
                int rel = sarg[g] - base;
                if (rel >= 0 && rel < 256) sforced[rel] = g;
            }
        }
    }
    __syncthreads();

    if (a >= A_TOTAL) return;

    float maxov = d_pmax[b][a];
    int   arg   = d_parg[b][a];
    int forced  = sforced[tid];

    bool pos;
    int aid;
    float4 gb;
    if (forced >= 0) {
        pos = true;  aid = sid[forced];  gb = sgt[forced];
    } else {
        pos = (maxov >= HI_T);  aid = sid[arg];  gb = sgt[arg];
    }

    int label = pos ? aid : ((maxov >= LO_T && maxov < HI_T) ? -1 : 0);

    float4 r = make_float4(0.f, 0.f, 0.f, 0.f);
    if (pos) {
        float4 an = anchors[a];
        float aw = __fsub_rn(an.z, an.x);
        float ah = __fsub_rn(an.w, an.y);
        float ax = __fadd_rn(an.x, __fmul_rn(0.5f, aw));
        float ay = __fadd_rn(an.y, __fmul_rn(0.5f, ah));
        float gw = __fsub_rn(gb.z, gb.x);
        float gh = __fsub_rn(gb.w, gb.y);
        float gx = __fadd_rn(gb.x, __fmul_rn(0.5f, gw));
        float gy = __fadd_rn(gb.y, __fmul_rn(0.5f, gh));
        r = make_float4(__fdiv_rn(__fsub_rn(gx, ax), aw),
                        __fdiv_rn(__fsub_rn(gy, ay), ah),
                        logf(__fdiv_rn(gw, aw)),
                        logf(__fdiv_rn(gh, ah)));
    }

    out[(size_t)b * A_TOTAL + a] = (float)label;
    float4* rout = (float4*)(out + (size_t)NB * A_TOTAL);
    rout[(size_t)b * A_TOTAL + a] = r;
}

extern "C" void kernel_launch(void* const* d_in, const int* in_sizes, int n_in,
                              void* d_out, int out_size) {
    const float4* bb      = (const float4*)d_in[0];  // bb_coord (16,32,4) f32
    const int*    ids     = (const int*)d_in[1];     // bird_ids (16,32) i32
    const float4* anchors = (const float4*)d_in[2];  // anchors (65472,4) f32
    float* out = (float*)d_out;

    init_table<<<(NB * NLVL * NG + 255) / 256, 256>>>();
    fused_kernel<<<dim3(ABLOCKS, NB), 256>>>(anchors, bb);
    finalize_kernel<<<dim3(ABLOCKS, NB), 256>>>(anchors, bb, ids, out);
}

// round 17
// speedup vs baseline: 7.8810x; 1.5246x over previous
#include <cuda_runtime.h>

#define NB 16
#define NG 32
#define NLVL 5
#define A_TOTAL 65472
#define ABLOCKS 256          // ceil(65472/256)
#define HI_T 0.5f
#define LO_T 0.4f

__constant__ int LVL_OFF[6] = {0, 49152, 61440, 64512, 65280, 65472};

// packed per-(b,level,g) first-max: (iou_bits << 32) | (0xFFFFFFFF - local_anchor_idx)
// default = (0.0, a_loc=0): matches jnp.argmax over an all-zero row.
#define TABLE_DEFAULT 0x00000000FFFFFFFFull
__device__ unsigned long long d_table[NB][NLVL][NG];
// per-(b,anchor) max IoU over g + first-max argmax
__device__ float d_pmax[NB][A_TOTAL];
__device__ int   d_parg[NB][A_TOTAL];

// ---------------------------------------------------------------------------
__global__ void init_table() {
    int i = blockIdx.x * blockDim.x + threadIdx.x;
    if (i < NB * NLVL * NG)
        ((unsigned long long*)d_table)[i] = TABLE_DEFAULT;
}

// ---------------------------------------------------------------------------
// Fused pass with spatial pruning: each thread = one (b, anchor).
// 1. Block computes its anchors' bounding box; GT boxes not intersecting it
//    have IoU == +0.0 for ALL block anchors (conservative) -> skip whole g.
// 2. Surviving g's: IoU computed once, division only when inter > 0 (0/x=+0.0).
// 3. Per-anchor max/argmax to scratch; per-(b,li,g) first-max via packed u64
//    block reduction + atomicMax, in <=16-g chunks (32 KB static smem).
// ---------------------------------------------------------------------------
__global__ void fused_kernel(const float4* __restrict__ anchors,
                             const float4* __restrict__ bb) {
    __shared__ unsigned long long s_pack[16][256];
    __shared__ float4 sgt[NG];
    __shared__ float  sag[NG];
    __shared__ int    s_glist[NG];
    __shared__ int    s_nact;
    __shared__ float  s_bx1[8], s_by1[8], s_bx2[8], s_by2[8];

    int b   = blockIdx.y;
    int tid = threadIdx.x;
    int a0  = blockIdx.x * 256;
    int a   = a0 + tid;
    int wid = tid >> 5, lane = tid & 31;

    int li = 0;
    while (a0 >= LVL_OFF[li + 1]) li++;

    if (tid < NG) {
        float4 g = bb[b * NG + tid];
        sgt[tid] = g;
        sag[tid] = __fmul_rn(__fsub_rn(g.z, g.x), __fsub_rn(g.w, g.y));
    }

    bool valid = a < A_TOTAL;
    float4 an = anchors[valid ? a : 0];   // invalid -> anchor 0: only loosens bbox
    float aa = __fmul_rn(__fsub_rn(an.z, an.x), __fsub_rn(an.w, an.y));
    int a_loc = a - LVL_OFF[li];
    unsigned int inv = 0xFFFFFFFFu - (unsigned int)a_loc;

    // block bounding box over member anchors (warp shuffle + cross-warp)
    float bx1 = an.x, by1 = an.y, bx2 = an.z, by2 = an.w;
    #pragma unroll
    for (int s = 16; s > 0; s >>= 1) {
        bx1 = fminf(bx1, __shfl_xor_sync(0xffffffffu, bx1, s));
        by1 = fminf(by1, __shfl_xor_sync(0xffffffffu, by1, s));
        bx2 = fmaxf(bx2, __shfl_xor_sync(0xffffffffu, bx2, s));
        by2 = fmaxf(by2, __shfl_xor_sync(0xffffffffu, by2, s));
    }
    if (lane == 0) { s_bx1[wid] = bx1; s_by1[wid] = by1; s_bx2[wid] = bx2; s_by2[wid] = by2; }
    __syncthreads();

    if (tid == 0) {
        float x1 = s_bx1[0], y1 = s_by1[0], x2 = s_bx2[0], y2 = s_by2[0];
        #pragma unroll
        for (int w = 1; w < 8; w++) {
            x1 = fminf(x1, s_bx1[w]); y1 = fminf(y1, s_by1[w]);
            x2 = fmaxf(x2, s_bx2[w]); y2 = fmaxf(y2, s_by2[w]);
        }
        int n = 0;
        for (int g = 0; g < NG; g++) {   // ascending: preserves first-max order
            float4 gt = sgt[g];
            if (fminf(x2, gt.z) > fmaxf(x1, gt.x) &&
                fminf(y2, gt.w) > fmaxf(y1, gt.y))
                s_glist[n++] = g;
        }
        s_nact = n;
    }
    __syncthreads();

    int nact = s_nact;
    float maxov = 0.0f;   // all-zero row -> argmax g=0 (matches jnp.argmax)
    int   arg = 0;

    for (int base = 0; base < nact; base += 16) {
        int cnt = min(16, nact - base);
        for (int k = 0; k < cnt; k++) {
            int g = s_glist[base + k];
            float v = 0.0f;
            if (valid) {
                float4 gt = sgt[g];
                float x1 = fmaxf(an.x, gt.x);
                float y1 = fmaxf(an.y, gt.y);
                float x2 = fminf(an.z, gt.z);
                float y2 = fminf(an.w, gt.w);
                float iw = fmaxf(__fsub_rn(x2, x1), 0.0f);
                float ih = fmaxf(__fsub_rn(y2, y1), 0.0f);
                float inter = __fmul_rn(iw, ih);
                if (inter > 0.0f) {   // 0/denom == +0.0 exactly
                    float denom = __fadd_rn(__fsub_rn(__fadd_rn(aa, sag[g]), inter), 1e-9f);
                    v = __fdiv_rn(inter, denom);
                }
            }
            s_pack[k][tid] = valid
                ? ((((unsigned long long)__float_as_uint(v)) << 32) | inv) : 0ull;
            if (v > maxov) { maxov = v; arg = g; }   // first-max over ascending g
        }
        __syncthreads();

        // reduce chunk: warp wid handles slots k = wid*2, wid*2+1
        #pragma unroll
        for (int kk = 0; kk < 2; kk++) {
            int k = wid * 2 + kk;
            if (k < cnt) {
                unsigned long long m = s_pack[k][lane];
                #pragma unroll
                for (int j = 1; j < 8; j++) {
                    unsigned long long t = s_pack[k][lane + 32 * j];
                    if (t > m) m = t;
                }
                #pragma unroll
                for (int s = 16; s > 0; s >>= 1) {
                    unsigned long long t = __shfl_xor_sync(0xffffffffu, m, s);
                    if (t > m) m = t;
                }
                if (lane == 0) atomicMax(&d_table[b][li][s_glist[base + k]], m);
            }
        }
        __syncthreads();
    }

    if (valid) { d_pmax[b][a] = maxov; d_parg[b][a] = arg; }
}

// ---------------------------------------------------------------------------
// Finalize: per (b, anchor) -> label + regression. Forced assignment is a
// per-block smem scatter (ascending g = last-g-wins, matching .at[].set()).
// ---------------------------------------------------------------------------
__global__ void finalize_kernel(const float4* __restrict__ anchors,
                                const float4* __restrict__ bb,
                                const int* __restrict__ ids,
                                float* __restrict__ out) {
    int b   = blockIdx.y;
    int tid = threadIdx.x;
    int a0  = blockIdx.x * 256;
    int a   = a0 + tid;

    __shared__ float4 sgt[NG];
    __shared__ int    sid[NG];
    __shared__ int    slvl[NG];
    __shared__ int    sarg[NG];
    __shared__ int    sforced[256];

    int li = 0;
    while (a0 >= LVL_OFF[li + 1]) li++;

    sforced[tid] = -1;
    if (tid < NG) {
        sgt[tid] = bb[b * NG + tid];
        sid[tid] = ids[b * NG + tid];
        unsigned long long p0 = d_table[b][0][tid];
        float mv = __uint_as_float((unsigned int)(p0 >> 32));
        int   ml = 0;
        #pragma unroll
        for (int l = 1; l < NLVL; l++) {
            unsigned long long p = d_table[b][l][tid];
            float v = __uint_as_float((unsigned int)(p >> 32));
            if (v > mv) { mv = v; ml = l; }   // first-max over levels
        }
        slvl[tid] = ml;
        unsigned long long pl = d_table[b][li][tid];
        sarg[tid] = (int)(0xFFFFFFFFu - (unsigned int)(pl & 0xFFFFFFFFu));
    }
    __syncthreads();

    if (tid == 0) {
        int base = a0 - LVL_OFF[li];
        for (int g = 0; g < NG; g++) {   // ascending g: last write wins
            if (slvl[g] == li) {
                int rel = sarg[g] - base;
                if (rel >= 0 && rel < 256) sforced[rel] = g;
            }
        }
    }
    __syncthreads();

    if (a >= A_TOTAL) return;

    float maxov = d_pmax[b][a];
    int   arg   = d_parg[b][a];
    int forced  = sforced[tid];

    bool pos;
    int aid;
    float4 gb;
    if (forced >= 0) {
        pos = true;  aid = sid[forced];  gb = sgt[forced];
    } else {
        pos = (maxov >= HI_T);  aid = sid[arg];  gb = sgt[arg];
    }

    int label = pos ? aid : ((maxov >= LO_T && maxov < HI_T) ? -1 : 0);

    float4 r = make_float4(0.f, 0.f, 0.f, 0.f);
    if (pos) {
        float4 an = anchors[a];
        float aw = __fsub_rn(an.z, an.x);
        float ah = __fsub_rn(an.w, an.y);
        float ax = __fadd_rn(an.x, __fmul_rn(0.5f, aw));
        float ay = __fadd_rn(an.y, __fmul_rn(0.5f, ah));
        float gw = __fsub_rn(gb.z, gb.x);
        float gh = __fsub_rn(gb.w, gb.y);
        float gx = __fadd_rn(gb.x, __fmul_rn(0.5f, gw));
        float gy = __fadd_rn(gb.y, __fmul_rn(0.5f, gh));
        r = make_float4(__fdiv_rn(__fsub_rn(gx, ax), aw),
                        __fdiv_rn(__fsub_rn(gy, ay), ah),
                        logf(__fdiv_rn(gw, aw)),
                        logf(__fdiv_rn(gh, ah)));
    }

    out[(size_t)b * A_TOTAL + a] = (float)label;
    float4* rout = (float4*)(out + (size_t)NB * A_TOTAL);
    rout[(size_t)b * A_TOTAL + a] = r;
}

extern "C" void kernel_launch(void* const* d_in, const int* in_sizes, int n_in,
                              void* d_out, int out_size) {
    const float4* bb      = (const float4*)d_in[0];  // bb_coord (16,32,4) f32
    const int*    ids     = (const int*)d_in[1];     // bird_ids (16,32) i32
    const float4* anchors = (const float4*)d_in[2];  // anchors (65472,4) f32
    float* out = (float*)d_out;

    init_table<<<(NB * NLVL * NG + 255) / 256, 256>>>();
    fused_kernel<<<dim3(ABLOCKS, NB), 256>>>(anchors, bb);
    finalize_kernel<<<dim3(ABLOCKS, NB), 256>>>(anchors, bb, ids, out);
}